// round 16
// baseline (speedup 1.0000x reference)
#include <cuda_runtime.h>
#include <cuda_bf16.h>
#include <stdint.h>
#include <math.h>

#define H 128
#define H4 32
#define NMAX 50176
#define WMAT 16384   // packed weight footprint in unsigneds per matrix (hi+lo)

// ---------------- device scratch (static, no allocation) ----------------
__device__ float g_h [NMAX * H];
__device__ float g_Pu[NMAX * H];
__device__ float g_Pv[NMAX * H];
__device__ float g_a1[NMAX * H];
__device__ float g_a2[NMAX * H];
__device__ float g_g [NMAX * H];
__device__ unsigned g_pack[24 * WMAT];   // bf16 hi/lo fragment-packed weights

// ---------------- helpers ----------------
__device__ __forceinline__ float silu(float x) { return x / (1.0f + __expf(-x)); }

__device__ __forceinline__ unsigned pbf2(float a, float b) {
    unsigned r;
    asm("cvt.rn.bf16x2.f32 %0, %1, %2;" : "=r"(r) : "f"(b), "f"(a));
    return r;
}

__device__ __forceinline__ void bsplit(float x, float& hi, float& lo) {
    __nv_bfloat16 h = __float2bfloat16(x);
    hi = __bfloat162float(h);
    lo = x - hi;
}

// m16n8k16 bf16 mma, D += A*B
__device__ __forceinline__ void mma16(float* c, const unsigned* a, uint2 b) {
    asm volatile(
        "mma.sync.aligned.m16n8k16.row.col.f32.bf16.bf16.f32 "
        "{%0,%1,%2,%3},{%4,%5,%6,%7},{%8,%9},{%0,%1,%2,%3};"
        : "+f"(c[0]), "+f"(c[1]), "+f"(c[2]), "+f"(c[3])
        : "r"(a[0]), "r"(a[1]), "r"(a[2]), "r"(a[3]), "r"(b.x), "r"(b.y));
}

// vectorized reduction atomic: p[0..3] += v
__device__ __forceinline__ void redv4(float* p, float4 v) {
    asm volatile("red.global.add.v4.f32 [%0], {%1,%2,%3,%4};"
                 :: "l"(p), "f"(v.x), "f"(v.y), "f"(v.z), "f"(v.w) : "memory");
}

__device__ __forceinline__ uint32_t s2u(const void* p) {
    uint32_t a;
    asm("{ .reg .u64 t; cvta.to.shared.u64 t, %1; cvt.u32.u64 %0, t; }" : "=r"(a) : "l"(p));
    return a;
}
__device__ __forceinline__ unsigned ld_acq(uint32_t a) {
    unsigned v;
    asm volatile("ld.acquire.cta.shared.u32 %0, [%1];" : "=r"(v) : "r"(a));
    return v;
}
__device__ __forceinline__ void st_rel(uint32_t a, unsigned v) {
    asm volatile("st.release.cta.shared.u32 [%0], %1;" :: "r"(a), "r"(v) : "memory");
}

// ---------------- weight packing ----------------
__global__ void k_pack(const float* __restrict__ Wu,  const float* __restrict__ Wv,
                       const float* __restrict__ eW2, const float* __restrict__ eW3,
                       const float* __restrict__ Wh,  const float* __restrict__ Wa1,
                       const float* __restrict__ Wa2, const float* __restrict__ uW2)
{
    int m = blockIdx.y;
    const float* src;
    if      (m < 4)  src = Wu  + m * H * H;
    else if (m < 8)  src = Wv  + (m - 4) * H * H;
    else if (m < 12) src = eW2 + (m - 8) * H * H;
    else if (m < 16) src = eW3 + (m - 12) * H * H;
    else if (m < 18) src = Wh  + (m - 16) * H * H;
    else if (m < 20) src = Wa1 + (m - 18) * H * H;
    else if (m < 22) src = Wa2 + (m - 20) * H * H;
    else             src = uW2 + (m - 22) * H * H;

    uint2* dhi = reinterpret_cast<uint2*>(g_pack + m * WMAT);
    uint2* dlo = dhi + 4096;

    for (int idx = blockIdx.x * blockDim.x + threadIdx.x; idx < 4096;
         idx += gridDim.x * blockDim.x) {
        int lane = idx & 31, kbnb = idx >> 5;
        int t = lane & 3, g = lane >> 2;
        int kb = kbnb & 7, nb = kbnb >> 3;
        int k0 = kb * 16 + 2 * t;
        int n  = nb * 8 + g;
        float w0 = src[(k0    ) * H + n];
        float w1 = src[(k0 + 1) * H + n];
        float w8 = src[(k0 + 8) * H + n];
        float w9 = src[(k0 + 9) * H + n];
        float h0, l0, h1, l1, h8, l8, h9, l9;
        bsplit(w0, h0, l0); bsplit(w1, h1, l1);
        bsplit(w8, h8, l8); bsplit(w9, h9, l9);
        dhi[idx] = make_uint2(pbf2(h0, h1), pbf2(h8, h9));
        dlo[idx] = make_uint2(pbf2(l0, l1), pbf2(l8, l9));
    }
}

// ---------------- misc kernels ----------------
__global__ void k_gather(const int* __restrict__ atom,
                         const float* __restrict__ emb,
                         float* __restrict__ h, int n)
{
    int i = blockIdx.x * blockDim.x + threadIdx.x;
    if (i >= n * H4) return;
    int row = i >> 5, col = i & 31;
    reinterpret_cast<float4*>(h)[i] =
        reinterpret_cast<const float4*>(emb)[atom[row] * H4 + col];
}

__global__ void k_zero2(float* __restrict__ a, float* __restrict__ b, int n4)
{
    int i = blockIdx.x * blockDim.x + threadIdx.x;
    if (i >= n4) return;
    float4 z = make_float4(0.f, 0.f, 0.f, 0.f);
    reinterpret_cast<float4*>(a)[i] = z;
    reinterpret_cast<float4*>(b)[i] = z;
}

__global__ void k_out(const float* __restrict__ h,
                      const float* __restrict__ outW,
                      const float* __restrict__ outb,
                      float* __restrict__ out, int n)
{
    int warp = (blockIdx.x * blockDim.x + threadIdx.x) >> 5;
    int lane = threadIdx.x & 31;
    if (warp >= n) return;
    float4 x = reinterpret_cast<const float4*>(h)[warp * H4 + lane];
    int k0 = lane * 4;
    float s0 = x.x * outW[(k0+0)*3+0] + x.y * outW[(k0+1)*3+0]
             + x.z * outW[(k0+2)*3+0] + x.w * outW[(k0+3)*3+0];
    float s1 = x.x * outW[(k0+0)*3+1] + x.y * outW[(k0+1)*3+1]
             + x.z * outW[(k0+2)*3+1] + x.w * outW[(k0+3)*3+1];
    float s2 = x.x * outW[(k0+0)*3+2] + x.y * outW[(k0+1)*3+2]
             + x.z * outW[(k0+2)*3+2] + x.w * outW[(k0+3)*3+2];
#pragma unroll
    for (int off = 16; off; off >>= 1) {
        s0 += __shfl_xor_sync(0xffffffffu, s0, off);
        s1 += __shfl_xor_sync(0xffffffffu, s1, off);
        s2 += __shfl_xor_sync(0xffffffffu, s2, off);
    }
    if (lane == 0) {
        out[warp*3+0] = s0 + outb[0];
        out[warp*3+1] = s1 + outb[1];
        out[warp*3+2] = s2 + outb[2];
    }
}

// ---------------- staging constants ----------------
#define SROW 68
#define SWARP 2176
#define ROW_WARPS 16
#define ROW2_WARPS 11

// edge kernel: 4 producer warps + 8 consumer warps, 8 slots
#define N_PROD 4
#define N_CONS 8
#define SLOTU 2216          // bufHi(1088) + bufLo(1088) + su(16) + sv(16) + flag + pad
#define SLOT_SU 2176
#define SLOT_SV 2192
#define SLOT_FLAG 2208

// load A fragments (hi+lo) for all 8 kb blocks from staging buffers
__device__ __forceinline__ void load_frags(const unsigned* bufHi, const unsigned* bufLo,
                                           int r, int t,
                                           unsigned ah[8][4], unsigned al[8][4])
{
#pragma unroll
    for (int kb = 0; kb < 8; ++kb) {
        int o0 = r * SROW + kb * 8 + t;
        int o1 = (r + 8) * SROW + kb * 8 + t;
        ah[kb][0] = bufHi[o0];     ah[kb][1] = bufHi[o1];
        ah[kb][2] = bufHi[o0 + 4]; ah[kb][3] = bufHi[o1 + 4];
        al[kb][0] = bufLo[o0];     al[kb][1] = bufLo[o1];
        al[kb][2] = bufLo[o0 + 4]; al[kb][3] = bufLo[o1 + 4];
    }
}

// bf16x3 split GEMM over TWO nb column blocks with FOUR independent chains.
__device__ __forceinline__ void gemm_nb_pair(float acc0[4], float acc1[4],
                                             const unsigned ah[8][4],
                                             const unsigned al[8][4],
                                             const uint2* sW, int nb0, int lane)
{
    const uint2* B0h = sW + nb0 * 256 + lane;
    const uint2* B0l = B0h + 4096;
    const uint2* B1h = B0h + 256;
    const uint2* B1l = B0l + 256;
    float e0[4] = {0.f,0.f,0.f,0.f};
    float e1[4] = {0.f,0.f,0.f,0.f};
#pragma unroll
    for (int kb = 0; kb < 8; kb += 2) {
        uint2 b0h = B0h[kb * 32],      b0l = B0l[kb * 32];
        uint2 b1h = B1h[kb * 32],      b1l = B1l[kb * 32];
        uint2 c0h = B0h[(kb+1) * 32],  c0l = B0l[(kb+1) * 32];
        uint2 c1h = B1h[(kb+1) * 32],  c1l = B1l[(kb+1) * 32];
        mma16(acc0, ah[kb],   b0h);  mma16(acc1, ah[kb],   b1h);
        mma16(e0,   ah[kb+1], c0h);  mma16(e1,   ah[kb+1], c1h);
        mma16(acc0, al[kb],   b0h);  mma16(acc1, al[kb],   b1h);
        mma16(e0,   al[kb+1], c0h);  mma16(e1,   al[kb+1], c1h);
        mma16(acc0, ah[kb],   b0l);  mma16(acc1, ah[kb],   b1l);
        mma16(e0,   ah[kb+1], c0l);  mma16(e1,   ah[kb+1], c1l);
    }
#pragma unroll
    for (int i = 0; i < 4; ++i) { acc0[i] += e0[i]; acc1[i] += e1[i]; }
}

// ---------------- tensor-core row GEMM ----------------
template<bool SILU_>
__global__ void __launch_bounds__(ROW_WARPS * 32, 1)
k_rowgemm_mma(const float* __restrict__ X, const unsigned* __restrict__ Wp,
              const float* __restrict__ bias, const float* __restrict__ R,
              float* __restrict__ Y, int n)
{
    extern __shared__ float smem[];
    unsigned* sW    = reinterpret_cast<unsigned*>(smem);
    float*    sBias = smem + WMAT;
    unsigned* bufAll = reinterpret_cast<unsigned*>(smem + WMAT + 128);

    {
        const uint4* s = reinterpret_cast<const uint4*>(Wp);
        uint4* d = reinterpret_cast<uint4*>(sW);
        for (int i = threadIdx.x; i < WMAT / 4; i += ROW_WARPS * 32) d[i] = s[i];
        if (threadIdx.x < H) sBias[threadIdx.x] = bias ? bias[threadIdx.x] : 0.f;
    }
    __syncthreads();

    int lane = threadIdx.x & 31;
    int warp = threadIdx.x >> 5;
    int r = lane >> 2, t = lane & 3;
    unsigned* bufHi = bufAll + warp * SWARP;
    unsigned* bufLo = bufHi + 1088;

    int nTiles = (n + 15) >> 4;
    for (int tile = blockIdx.x * ROW_WARPS + warp; tile < nTiles;
         tile += gridDim.x * ROW_WARPS) {
        int row0 = tile * 16;
#pragma unroll
        for (int e = 0; e < 16; ++e) {
            int rw = row0 + e;
            float4 x = (rw < n) ? reinterpret_cast<const float4*>(X)[rw * H4 + lane]
                                : make_float4(0.f, 0.f, 0.f, 0.f);
            float h0,l0,h1,l1,h2,l2,h3,l3;
            bsplit(x.x,h0,l0); bsplit(x.y,h1,l1); bsplit(x.z,h2,l2); bsplit(x.w,h3,l3);
            *reinterpret_cast<uint2*>(bufHi + e * SROW + 2 * lane) = make_uint2(pbf2(h0,h1), pbf2(h2,h3));
            *reinterpret_cast<uint2*>(bufLo + e * SROW + 2 * lane) = make_uint2(pbf2(l0,l1), pbf2(l2,l3));
        }
        __syncwarp();
        unsigned ah[8][4], al[8][4];
        load_frags(bufHi, bufLo, r, t, ah, al);
        __syncwarp();

        int gr_lo = row0 + r, gr_hi = row0 + r + 8;
        bool ok_lo = gr_lo < n, ok_hi = gr_hi < n;

#pragma unroll 2
        for (int nb = 0; nb < 16; nb += 2) {
            float acc0[4] = {0.f,0.f,0.f,0.f};
            float acc1[4] = {0.f,0.f,0.f,0.f};
            gemm_nb_pair(acc0, acc1, ah, al, reinterpret_cast<const uint2*>(sW), nb, lane);

#pragma unroll
            for (int s = 0; s < 2; ++s) {
                float* acc = s ? acc1 : acc0;
                int c0 = (nb + s) * 8 + 2 * t;
                float2 p = *reinterpret_cast<const float2*>(&sBias[c0]);
                float v0 = acc[0] + p.x, v1 = acc[1] + p.y;
                float v2 = acc[2] + p.x, v3 = acc[3] + p.y;
                if (R) {
                    if (ok_lo) {
                        float2 r0 = *reinterpret_cast<const float2*>(&R[gr_lo * H + c0]);
                        v0 += r0.x; v1 += r0.y;
                    }
                    if (ok_hi) {
                        float2 r1 = *reinterpret_cast<const float2*>(&R[gr_hi * H + c0]);
                        v2 += r1.x; v3 += r1.y;
                    }
                }
                if (SILU_) { v0 = silu(v0); v1 = silu(v1); v2 = silu(v2); v3 = silu(v3); }
                if (ok_lo) *reinterpret_cast<float2*>(&Y[gr_lo * H + c0]) = make_float2(v0, v1);
                if (ok_hi) *reinterpret_cast<float2*>(&Y[gr_hi * H + c0]) = make_float2(v2, v3);
            }
        }
    }
}

// ---------------- dual-output row GEMM: Pu = X@Wu, Pv = X@Wv ----------------
__global__ void __launch_bounds__(ROW2_WARPS * 32, 1)
k_rowgemm2(const float* __restrict__ X,
           const unsigned* __restrict__ WpU, const unsigned* __restrict__ WpV,
           float* __restrict__ YU, float* __restrict__ YV, int n)
{
    extern __shared__ float smem[];
    unsigned* sWu = reinterpret_cast<unsigned*>(smem);
    unsigned* sWv = sWu + WMAT;
    unsigned* bufAll = sWu + 2 * WMAT;

    {
        const uint4* su = reinterpret_cast<const uint4*>(WpU);
        const uint4* sv = reinterpret_cast<const uint4*>(WpV);
        uint4* du = reinterpret_cast<uint4*>(sWu);
        uint4* dv = reinterpret_cast<uint4*>(sWv);
        for (int i = threadIdx.x; i < WMAT / 4; i += ROW2_WARPS * 32) {
            du[i] = su[i]; dv[i] = sv[i];
        }
    }
    __syncthreads();

    int lane = threadIdx.x & 31;
    int warp = threadIdx.x >> 5;
    int r = lane >> 2, t = lane & 3;
    unsigned* bufHi = bufAll + warp * SWARP;
    unsigned* bufLo = bufHi + 1088;

    int nTiles = (n + 15) >> 4;
    for (int tile = blockIdx.x * ROW2_WARPS + warp; tile < nTiles;
         tile += gridDim.x * ROW2_WARPS) {
        int row0 = tile * 16;
#pragma unroll
        for (int e = 0; e < 16; ++e) {
            int rw = row0 + e;
            float4 x = (rw < n) ? reinterpret_cast<const float4*>(X)[rw * H4 + lane]
                                : make_float4(0.f, 0.f, 0.f, 0.f);
            float h0,l0,h1,l1,h2,l2,h3,l3;
            bsplit(x.x,h0,l0); bsplit(x.y,h1,l1); bsplit(x.z,h2,l2); bsplit(x.w,h3,l3);
            *reinterpret_cast<uint2*>(bufHi + e * SROW + 2 * lane) = make_uint2(pbf2(h0,h1), pbf2(h2,h3));
            *reinterpret_cast<uint2*>(bufLo + e * SROW + 2 * lane) = make_uint2(pbf2(l0,l1), pbf2(l2,l3));
        }
        __syncwarp();
        unsigned ah[8][4], al[8][4];
        load_frags(bufHi, bufLo, r, t, ah, al);
        __syncwarp();

        int gr_lo = row0 + r, gr_hi = row0 + r + 8;
        bool ok_lo = gr_lo < n, ok_hi = gr_hi < n;

#pragma unroll 2
        for (int nb = 0; nb < 16; nb += 2) {
            float accU0[4] = {0.f,0.f,0.f,0.f};
            float accU1[4] = {0.f,0.f,0.f,0.f};
            gemm_nb_pair(accU0, accU1, ah, al, reinterpret_cast<const uint2*>(sWu), nb, lane);
            int c0 = nb * 8 + 2 * t, c1 = c0 + 8;
            if (ok_lo) {
                *reinterpret_cast<float2*>(&YU[gr_lo * H + c0]) = make_float2(accU0[0], accU0[1]);
                *reinterpret_cast<float2*>(&YU[gr_lo * H + c1]) = make_float2(accU1[0], accU1[1]);
            }
            if (ok_hi) {
                *reinterpret_cast<float2*>(&YU[gr_hi * H + c0]) = make_float2(accU0[2], accU0[3]);
                *reinterpret_cast<float2*>(&YU[gr_hi * H + c1]) = make_float2(accU1[2], accU1[3]);
            }

            float accV0[4] = {0.f,0.f,0.f,0.f};
            float accV1[4] = {0.f,0.f,0.f,0.f};
            gemm_nb_pair(accV0, accV1, ah, al, reinterpret_cast<const uint2*>(sWv), nb, lane);
            if (ok_lo) {
                *reinterpret_cast<float2*>(&YV[gr_lo * H + c0]) = make_float2(accV0[0], accV0[1]);
                *reinterpret_cast<float2*>(&YV[gr_lo * H + c1]) = make_float2(accV1[0], accV1[1]);
            }
            if (ok_hi) {
                *reinterpret_cast<float2*>(&YV[gr_hi * H + c0]) = make_float2(accV0[2], accV0[3]);
                *reinterpret_cast<float2*>(&YV[gr_hi * H + c1]) = make_float2(accV1[2], accV1[3]);
            }
        }
    }
}

// ---------------- warp-specialized fused edge block ----------------
// Warps 0..3: producers (gather Pu/Pv, compute t1, stage bf16 hi/lo into slot).
// Warps 4..11: consumers (frag load, GEMM1 -> GEMM2, red.v4 scatter).
// Producer p feeds consumers {2p, 2p+1}. Tile j of this CTA -> consumer j%8.
// Slot handshake: flag==0 empty, flag==1 full (acquire/release, CTA scope).
__global__ void __launch_bounds__((N_PROD + N_CONS) * 32, 1)
k_edge_mma(const float* __restrict__ Pu, const float* __restrict__ Pv,
           const float* __restrict__ dis,
           const int* __restrict__ idu, const int* __restrict__ idv,
           const float* __restrict__ wdis, const float* __restrict__ b1,
           const unsigned* __restrict__ W2p, const float* __restrict__ b2,
           const unsigned* __restrict__ W3p, const float* __restrict__ b3,
           float* __restrict__ aOut, int E)
{
    extern __shared__ float smem[];
    unsigned* sW2 = reinterpret_cast<unsigned*>(smem);          // WMAT
    unsigned* sW3 = reinterpret_cast<unsigned*>(smem) + WMAT;   // WMAT
    float* sB2 = smem + 2 * WMAT;
    float* sB3 = smem + 2 * WMAT + 128;
    float* sWd = smem + 2 * WMAT + 256;
    float* sB1 = smem + 2 * WMAT + 384;
    unsigned* slotAll = reinterpret_cast<unsigned*>(smem + 2 * WMAT + 512);

    const int NW = N_PROD + N_CONS;
    {
        const uint4* s2 = reinterpret_cast<const uint4*>(W2p);
        const uint4* s3 = reinterpret_cast<const uint4*>(W3p);
        uint4* d2 = reinterpret_cast<uint4*>(sW2);
        uint4* d3 = reinterpret_cast<uint4*>(sW3);
        for (int i = threadIdx.x; i < WMAT / 4; i += NW * 32) { d2[i] = s2[i]; d3[i] = s3[i]; }
        if (threadIdx.x < H) {
            sB2[threadIdx.x] = b2[threadIdx.x];
            sB3[threadIdx.x] = b3[threadIdx.x];
            sWd[threadIdx.x] = wdis[threadIdx.x];
            sB1[threadIdx.x] = b1[threadIdx.x];
        }
        if (threadIdx.x < N_CONS)
            slotAll[threadIdx.x * SLOTU + SLOT_FLAG] = 0;
    }
    __syncthreads();

    int lane = threadIdx.x & 31;
    int warp = threadIdx.x >> 5;

    int nT = (E + 15) >> 4;
    // tiles of this CTA: g = j * gridDim.x + blockIdx.x, j in [0, Jcta)
    int Jcta = (nT - 1 - (int)blockIdx.x) / (int)gridDim.x + 1;
    if ((int)blockIdx.x >= nT) Jcta = 0;

    const float4* Pu4 = reinterpret_cast<const float4*>(Pu);
    const float4* Pv4 = reinterpret_cast<const float4*>(Pv);

    if (warp < N_PROD) {
        // ================= PRODUCER =================
        int p = warp;
        float4 wd  = reinterpret_cast<const float4*>(sWd)[lane];
        float4 bb1 = reinterpret_cast<const float4*>(sB1)[lane];

        for (int k = 0; ; ++k) {
            int j = 2 * p + (k & 1) + (k >> 1) * 8;
            if (j >= Jcta) break;
            int c = j & 7;
            unsigned* slot = slotAll + c * SLOTU;
            uint32_t flagA = s2u(slot + SLOT_FLAG);
            int g = j * (int)gridDim.x + (int)blockIdx.x;
            int e0 = g * 16;

            int u_s = 0, v_s = 0; float d_s = 0.f;
            if (lane < 16 && e0 + lane < E) {
                u_s = idu[e0 + lane]; v_s = idv[e0 + lane]; d_s = dis[e0 + lane];
            }

            // wait slot empty
            while (ld_acq(flagA) != 0) __nanosleep(32);

            unsigned* bufHi = slot;
            unsigned* bufLo = slot + 1088;

            float4 fu[4], fv[4];
#pragma unroll
            for (int q = 0; q < 4; ++q) {
                int u = __shfl_sync(0xffffffffu, u_s, q);
                int v = __shfl_sync(0xffffffffu, v_s, q);
                fu[q] = Pu4[(size_t)u * H4 + lane];
                fv[q] = Pv4[(size_t)v * H4 + lane];
            }
#pragma unroll
            for (int e = 0; e < 16; ++e) {
                float4 pu = fu[e & 3];
                float4 pv = fv[e & 3];
                if (e < 12) {
                    int u = __shfl_sync(0xffffffffu, u_s, e + 4);
                    int v = __shfl_sync(0xffffffffu, v_s, e + 4);
                    fu[e & 3] = Pu4[(size_t)u * H4 + lane];
                    fv[e & 3] = Pv4[(size_t)v * H4 + lane];
                }
                float d = __shfl_sync(0xffffffffu, d_s, e);
                float t0 = silu(pu.x + pv.x + d * wd.x + bb1.x);
                float t1 = silu(pu.y + pv.y + d * wd.y + bb1.y);
                float t2 = silu(pu.z + pv.z + d * wd.z + bb1.z);
                float t3 = silu(pu.w + pv.w + d * wd.w + bb1.w);
                float h0,l0,h1,l1,h2,l2,h3,l3;
                bsplit(t0,h0,l0); bsplit(t1,h1,l1); bsplit(t2,h2,l2); bsplit(t3,h3,l3);
                *reinterpret_cast<uint2*>(bufHi + e * SROW + 2 * lane) = make_uint2(pbf2(h0,h1), pbf2(h2,h3));
                *reinterpret_cast<uint2*>(bufLo + e * SROW + 2 * lane) = make_uint2(pbf2(l0,l1), pbf2(l2,l3));
            }
            if (lane < 16) {
                slot[SLOT_SU + lane] = (unsigned)u_s;
                slot[SLOT_SV + lane] = (unsigned)v_s;
            }
            __syncwarp();
            if (lane == 0) st_rel(flagA, 1u);   // release: staging visible
        }
    } else {
        // ================= CONSUMER =================
        int c = warp - N_PROD;
        int r = lane >> 2, t = lane & 3;
        unsigned* slot = slotAll + c * SLOTU;
        uint32_t flagA = s2u(slot + SLOT_FLAG);
        unsigned* bufHi = slot;
        unsigned* bufLo = slot + 1088;
        float* scat = reinterpret_cast<float*>(slot);   // reuse after frag load

        for (int k = 0; ; ++k) {
            int j = c + 8 * k;
            if (j >= Jcta) break;
            int g = j * (int)gridDim.x + (int)blockIdx.x;
            int e0 = g * 16;

            while (ld_acq(flagA) != 1u) __nanosleep(32);

            unsigned ah[8][4], al[8][4];
            load_frags(bufHi, bufLo, r, t, ah, al);
            __syncwarp();

            // ---- GEMM1: t2 = silu(t1 @ W2 + b2) -> GEMM2 A-frags ----
            unsigned bh[8][4], bl[8][4];
#pragma unroll
            for (int kb = 0; kb < 8; ++kb) {
                float acc0[4] = {0.f,0.f,0.f,0.f};
                float acc1[4] = {0.f,0.f,0.f,0.f};
                gemm_nb_pair(acc0, acc1, ah, al, reinterpret_cast<const uint2*>(sW2),
                             2 * kb, lane);
#pragma unroll
                for (int s = 0; s < 2; ++s) {
                    float* acc = s ? acc1 : acc0;
                    int c0 = (2 * kb + s) * 8 + 2 * t;
                    float2 p = *reinterpret_cast<const float2*>(&sB2[c0]);
                    float v0 = silu(acc[0] + p.x), v1 = silu(acc[1] + p.y);
                    float v2 = silu(acc[2] + p.x), v3 = silu(acc[3] + p.y);
                    float h0,l0,h1,l1,h2,l2,h3,l3;
                    bsplit(v0,h0,l0); bsplit(v1,h1,l1);
                    bsplit(v2,h2,l2); bsplit(v3,h3,l3);
                    bh[kb][2*s]     = pbf2(h0, h1);  bl[kb][2*s]     = pbf2(l0, l1);
                    bh[kb][2*s + 1] = pbf2(h2, h3);  bl[kb][2*s + 1] = pbf2(l2, l3);
                }
            }

            // ---- GEMM2: m = t2 @ W3 + b3 -> stage fp32 into scat ----
#pragma unroll 2
            for (int nb = 0; nb < 16; nb += 2) {
                float acc0[4] = {0.f,0.f,0.f,0.f};
                float acc1[4] = {0.f,0.f,0.f,0.f};
                gemm_nb_pair(acc0, acc1, bh, bl, reinterpret_cast<const uint2*>(sW3),
                             nb, lane);
#pragma unroll
                for (int s = 0; s < 2; ++s) {
                    float* acc = s ? acc1 : acc0;
                    int c0 = (nb + s) * 8 + 2 * t;
                    float2 q = *reinterpret_cast<const float2*>(&sB3[c0]);
                    *reinterpret_cast<float2*>(&scat[r * 132 + c0])       = make_float2(acc[0] + q.x, acc[1] + q.y);
                    *reinterpret_cast<float2*>(&scat[(r + 8) * 132 + c0]) = make_float2(acc[2] + q.x, acc[3] + q.y);
                }
            }
            __syncwarp();

            // ---- scatter: red.v4 to aOut[u], aOut[v] ----
#pragma unroll 4
            for (int e = 0; e < 16; ++e) {
                if (e0 + e >= E) break;
                int u = (int)slot[SLOT_SU + e];
                int v = (int)slot[SLOT_SV + e];
                float4 mv = *reinterpret_cast<const float4*>(&scat[e * 132 + 4 * lane]);
                redv4(aOut + (size_t)u * H + 4 * lane, mv);
                redv4(aOut + (size_t)v * H + 4 * lane, mv);
            }
            __syncwarp();
            if (lane == 0) st_rel(flagA, 0u);   // release: slot free
        }
    }
}

// ---------------- host launch ----------------
extern "C" void kernel_launch(void* const* d_in, const int* in_sizes, int n_in,
                              void* d_out, int out_size)
{
    const int*   atom = (const int*)  d_in[0];
    const float* dis1 = (const float*)d_in[1];
    const float* dis2 = (const float*)d_in[2];
    const int*   id1u = (const int*)  d_in[3];
    const int*   id1v = (const int*)  d_in[4];
    const int*   id2u = (const int*)  d_in[5];
    const int*   id2v = (const int*)  d_in[6];
    const float* emb  = (const float*)d_in[7];
    const float* Wu   = (const float*)d_in[8];
    const float* Wv   = (const float*)d_in[9];
    const float* Wdis = (const float*)d_in[10];
    const float* eb1  = (const float*)d_in[11];
    const float* eW2  = (const float*)d_in[12];
    const float* eb2  = (const float*)d_in[13];
    const float* eW3  = (const float*)d_in[14];
    const float* eb3  = (const float*)d_in[15];
    const float* Wh   = (const float*)d_in[16];
    const float* Wa1  = (const float*)d_in[17];
    const float* Wa2  = (const float*)d_in[18];
    const float* ub1  = (const float*)d_in[19];
    const float* uW2  = (const float*)d_in[20];
    const float* ub2  = (const float*)d_in[21];
    const float* outW = (const float*)d_in[22];
    const float* outb = (const float*)d_in[23];

    int n = in_sizes[0];
    int E = in_sizes[3];
    if (n > NMAX) return;

    float *h, *Pu, *Pv, *a1, *a2, *g;
    unsigned* pk;
    cudaGetSymbolAddress((void**)&h,  g_h);
    cudaGetSymbolAddress((void**)&Pu, g_Pu);
    cudaGetSymbolAddress((void**)&Pv, g_Pv);
    cudaGetSymbolAddress((void**)&a1, g_a1);
    cudaGetSymbolAddress((void**)&a2, g_a2);
    cudaGetSymbolAddress((void**)&g,  g_g);
    cudaGetSymbolAddress((void**)&pk, g_pack);

    const int SM_ROW  = (WMAT + 128) * 4 + ROW_WARPS * SWARP * 4;      // 205312 B
    const int SM_ROW2 = 2 * WMAT * 4 + ROW2_WARPS * SWARP * 4;         // 226816 B
    const int SM_EDGE = (2 * WMAT + 512) * 4 + N_CONS * SLOTU * 4;     // 204032 B

    cudaFuncSetAttribute(k_rowgemm_mma<false>,
                         cudaFuncAttributeMaxDynamicSharedMemorySize, SM_ROW);
    cudaFuncSetAttribute(k_rowgemm_mma<true>,
                         cudaFuncAttributeMaxDynamicSharedMemorySize, SM_ROW);
    cudaFuncSetAttribute(k_rowgemm2,
                         cudaFuncAttributeMaxDynamicSharedMemorySize, SM_ROW2);
    cudaFuncSetAttribute(k_edge_mma,
                         cudaFuncAttributeMaxDynamicSharedMemorySize, SM_EDGE);

    int gthreads = n * H4;
    int gblocks  = (gthreads + 255) / 256;

    k_pack<<<dim3(2, 24), 256>>>(Wu, Wv, eW2, eW3, Wh, Wa1, Wa2, uW2);
    k_gather<<<gblocks, 256>>>(atom, emb, h, n);

    for (int L = 0; L < 2; ++L) {
        k_zero2<<<gblocks, 256>>>(a1, a2, n * H4);

        int i1 = 2 * L, i2 = 2 * L + 1;

        // edge block i1 (graph 1) -> a1
        k_rowgemm2<<<148, ROW2_WARPS * 32, SM_ROW2>>>(
            h, pk + (0 + i1) * WMAT, pk + (4 + i1) * WMAT, Pu, Pv, n);
        k_edge_mma<<<148, (N_PROD + N_CONS) * 32, SM_EDGE>>>(
            Pu, Pv, dis1, id1u, id1v,
            Wdis + i1 * H, eb1 + i1 * H,
            pk + (8 + i1) * WMAT, eb2 + i1 * H,
            pk + (12 + i1) * WMAT, eb3 + i1 * H, a1, E);

        // edge block i2 (graph 2) -> a2
        k_rowgemm2<<<148, ROW2_WARPS * 32, SM_ROW2>>>(
            h, pk + (0 + i2) * WMAT, pk + (4 + i2) * WMAT, Pu, Pv, n);
        k_edge_mma<<<148, (N_PROD + N_CONS) * 32, SM_EDGE>>>(
            Pu, Pv, dis2, id2u, id2v,
            Wdis + i2 * H, eb1 + i2 * H,
            pk + (8 + i2) * WMAT, eb2 + i2 * H,
            pk + (12 + i2) * WMAT, eb3 + i2 * H, a2, E);

        // atom update L
        k_rowgemm_mma<false><<<148, ROW_WARPS * 32, SM_ROW>>>(h,  pk + (16 + L) * WMAT, 0,           0, g, n);
        k_rowgemm_mma<false><<<148, ROW_WARPS * 32, SM_ROW>>>(a1, pk + (18 + L) * WMAT, 0,           g, g, n);
        k_rowgemm_mma<true ><<<148, ROW_WARPS * 32, SM_ROW>>>(a2, pk + (20 + L) * WMAT, ub1 + L * H, g, g, n);
        k_rowgemm_mma<false><<<148, ROW_WARPS * 32, SM_ROW>>>(g,  pk + (22 + L) * WMAT, ub2 + L * H, h, h, n);
    }

    k_out<<<gblocks, 256>>>(h, outW, outb, (float*)d_out, n);
}